// round 14
// baseline (speedup 1.0000x reference)
#include <cuda_runtime.h>
#include <cstdint>

#define BATCH 16
#define CIN   256
#define COUT  256
#define HH    64
#define WW    64
#define LAT   512
#define KTOT  2304

// ---------------- scratch (device globals; no allocation) ----------------
__device__ __align__(16) float g_s[BATCH * CIN];
__device__ __align__(16) float g_d[BATCH * COUT];
__device__ __align__(16) float g_wss[CIN * COUT];
// A panels, fragment-major: [b][cot][chunk(72)][frag(32)][lane(32)] float4
__device__ __align__(16) float g_wA[(size_t)BATCH * 2 * KTOT * 128];

__device__ __forceinline__ uint32_t tf32_rna(float v) {
    uint32_t u;
    asm("cvt.rna.tf32.f32 %0, %1;" : "=r"(u) : "f"(v));
    return u;
}

// ---------------- prep kernels ----------------
__global__ void fused1_kernel(const float* __restrict__ style,
                              const float* __restrict__ style_w,
                              const float* __restrict__ style_b,
                              const float* __restrict__ weight) {
    if (blockIdx.x < 16) {
        __shared__ float st[LAT];
        int b = blockIdx.x, tid = threadIdx.x;
        st[tid]       = style[b * LAT + tid];
        st[tid + 256] = style[b * LAT + tid + 256];
        __syncthreads();
        float acc = style_b[tid];
#pragma unroll 8
        for (int l = 0; l < LAT; l++) acc += st[l] * style_w[l * CIN + tid];
        g_s[b * CIN + tid] = acc;
    } else {
        int ci = blockIdx.x - 16, co = threadIdx.x;
        const float* wp = weight + co * (CIN * 9) + ci * 9;
        float s = 0.f;
#pragma unroll
        for (int t = 0; t < 9; t++) { float v = wp[t]; s += v * v; }
        g_wss[ci * COUT + co] = s;
    }
}

__global__ void d_kernel() {
    __shared__ float s2[CIN];
    int b = blockIdx.x, co = threadIdx.x;
    float sv = g_s[b * CIN + co];
    s2[co] = sv * sv;
    __syncthreads();
    float acc = 1e-8f;
#pragma unroll 8
    for (int ci = 0; ci < CIN; ci++) acc += g_wss[ci * COUT + co] * s2[ci];
    g_d[b * COUT + co] = rsqrtf(acc);
}

// Fragment-major modulated weights (validated layout).
__global__ void wa_kernel(const float* __restrict__ weight) {
    int o = blockIdx.x * 256 + threadIdx.x;
    int lane = o & 31; int t = o >> 5;
    int mt = t & 3;  t >>= 2;
    int wm = t & 1;  t >>= 1;
    int ks = t & 3;  t >>= 2;
    int chunk = t % 72; t /= 72;
    int cot = t & 1; int b = t >> 1;
    int g = lane >> 2, tig = lane & 3;
    int kk  = ks * 8 + tig;
    int cig = chunk / 9, tap = chunk - 9 * cig;
    int ci  = cig * 32 + kk;
    int co  = cot * 128 + wm * 64 + mt * 16 + g;
    float s0 = g_s[b * CIN + ci],  s1 = g_s[b * CIN + ci + 4];
    float d0 = g_d[b * COUT + co], d1 = g_d[b * COUT + co + 8];
    float4 r;
    r.x = __uint_as_float(tf32_rna(weight[(co * CIN + ci) * 9 + tap]           * s0 * d0));
    r.y = __uint_as_float(tf32_rna(weight[((co + 8) * CIN + ci) * 9 + tap]     * s0 * d1));
    r.z = __uint_as_float(tf32_rna(weight[(co * CIN + ci + 4) * 9 + tap]       * s1 * d0));
    r.w = __uint_as_float(tf32_rna(weight[((co + 8) * CIN + ci + 4) * 9 + tap] * s1 * d1));
    ((float4*)g_wA)[o] = r;
}

// ---------------- main: A fragments direct from gmem (L2), slab-only smem ----------------
// CTA: M=128 co x N=128 px (2 rows). 8 warps (2x4), warp tile 64x32, 2 CTA/SM.
// A: LDG.128 fragments straight from fragment-major g_wA (L2-resident panel,
//    L1 hits across the 4 wn-warps reading the same lines). No A smem, no A STS.
// B: double-buffered tap-shift slab, cp.async-prefetched in 8 pieces (taps 0..7).
// __syncthreads only at ci-group boundaries: 8 barriers total instead of 72.
#define SLAB_P    296                  // floats per ci (4*68 + 24 pad); %32==8 -> conflict-free
#define SLAB_R    68                   // floats per image row (cols 0..3 pad, data 4..67)
#define SLAB_FLOATS (32 * SLAB_P)      // 9472
#define SLAB_BYTES (SLAB_FLOATS * 4)   // 37888
#define SMEM_BYTES (2 * SLAB_BYTES)    // 75776 -> 2 CTAs/SM easily

#define CP16_CG(dst, src) \
    asm volatile("cp.async.cg.shared.global [%0], [%1], 16;" :: "r"(dst), "l"(src))
#define CP_COMMIT()   asm volatile("cp.async.commit_group;" ::: "memory")
#define CP_WAIT_ALL() asm volatile("cp.async.wait_group 0;" ::: "memory")

#define MMA_TF32(c, a, b0, b1)                                                 \
    asm volatile("mma.sync.aligned.m16n8k8.row.col.f32.tf32.tf32.f32 "         \
        "{%0,%1,%2,%3}, {%4,%5,%6,%7}, {%8,%9}, {%0,%1,%2,%3};"                \
        : "+f"((c)[0]), "+f"((c)[1]), "+f"((c)[2]), "+f"((c)[3])               \
        : "r"((a).x), "r"((a).y), "r"((a).z), "r"((a).w), "r"(b0), "r"(b1))

__global__ void __launch_bounds__(256, 2)
conv_mma(const float* __restrict__ x, const float* __restrict__ noise,
         const float* __restrict__ bias, const float* __restrict__ nwptr,
         float* __restrict__ out) {
    extern __shared__ __align__(16) float slabs[];
    const uint32_t sbase = (uint32_t)__cvta_generic_to_shared(slabs);

    const int tid  = threadIdx.x;
    const int w    = tid >> 5;
    const int lane = tid & 31;
    const int g    = lane >> 2;
    const int tig  = lane & 3;
    const int wm   = w >> 2;
    const int wn   = w & 3;

    const int y0     = blockIdx.x * 2;
    const int coBase = blockIdx.y * 128;
    const int b      = blockIdx.z;

    const float* xb = x + (size_t)b * (CIN * HH * WW);
    const uint4* wa4 = (const uint4*)g_wA + ((size_t)(b * 2 + blockIdx.y)) * (72 * 1024);

    // zero both slabs once (pads + out-of-range rows stay zero forever)
    for (int i = tid; i < 2 * SLAB_FLOATS / 4; i += 256)
        ((float4*)slabs)[i] = make_float4(0.f, 0.f, 0.f, 0.f);

    float c[4][4][4];
#pragma unroll
    for (int mt = 0; mt < 4; mt++)
#pragma unroll
        for (int nt = 0; nt < 4; nt++)
#pragma unroll
            for (int i = 0; i < 4; i++) c[mt][nt][i] = 0.f;

    // one slab piece: 256 of the 2048 float4 (rows 0..127 x 16 float4)
    auto load_slab_piece = [&](int cig, int sb, int piece) {
        const uint32_t slbase = sbase + sb * SLAB_BYTES;
        int o   = piece * 256 + tid;
        int row = o >> 4;              // (ci,ry) pair 0..127
        int f   = o & 15;
        int ci  = row >> 2;
        int ry  = row & 3;
        int y   = y0 - 1 + ry;
        if ((unsigned)y < HH) {
            const float* src = xb + (size_t)(cig * 32 + ci) * (HH * WW) + y * WW + f * 4;
            CP16_CG(slbase + (ci * SLAB_P + ry * SLAB_R + 4 + f * 4) * 4, src);
        }
    };

    __syncthreads();                   // zeroing visible before cp.async writes
#pragma unroll
    for (int p = 0; p < 8; p++) load_slab_piece(0, 0, p);
    CP_COMMIT();
    CP_WAIT_ALL();
    __syncthreads();

    // per-thread B fragment base (excl. ks/tap terms); data col = 4 + xx
    const int bfrag0 = tig * SLAB_P + (wn >> 1) * SLAB_R + (wn & 1) * 32 + g + 3;

    for (int cig = 0; cig < 8; cig++) {
        const float* slab = slabs + (cig & 1) * SLAB_FLOATS;
#pragma unroll
        for (int tap = 0; tap < 9; tap++) {
            const int chunk = cig * 9 + tap;

            // spread next ci-group's slab prefetch over taps 0..7
            if (tap < 8 && cig + 1 < 8) {
                load_slab_piece(cig + 1, (cig + 1) & 1, tap);
                CP_COMMIT();
            }

            const int ky = tap / 3;
            const int kx = tap - ky * 3;
            const float* bptr = slab + bfrag0 + ky * SLAB_R + kx;
            const uint4* Ag = wa4 + chunk * 1024 + wm * 128 + lane;

#pragma unroll
            for (int ks = 0; ks < 4; ks++) {
                const uint4* ap = Ag + ks * 256;       // (ks*2+wm)*4*32 grouped
                uint4 a[4];
#pragma unroll
                for (int mt = 0; mt < 4; mt++)
                    a[mt] = ap[mt * 32];
                const float* bk = bptr + ks * (8 * SLAB_P);
                uint32_t b0[4], b1[4];
#pragma unroll
                for (int nt = 0; nt < 4; nt++) {
                    b0[nt] = __float_as_uint(bk[nt * 8]);
                    b1[nt] = __float_as_uint(bk[nt * 8 + 4 * SLAB_P]);
                }
#pragma unroll
                for (int mt = 0; mt < 4; mt++)
#pragma unroll
                    for (int nt = 0; nt < 4; nt++)
                        MMA_TF32(c[mt][nt], a[mt], b0[nt], b1[nt]);
            }
        }
        // swap to next slab: all prefetch pieces have had >= 1 chunk of slack
        if (cig + 1 < 8) {
            CP_WAIT_ALL();
            __syncthreads();
        }
    }

    // ---- epilogue: noise + bias + leaky_relu * sqrt(2)
    {
        const float nw = nwptr[0];
        const int y = y0 + (wn >> 1);
        const float* nzrow = noise + (size_t)b * (HH * WW) + y * WW;
#pragma unroll
        for (int mt = 0; mt < 4; mt++) {
            int co0 = coBase + wm * 64 + mt * 16 + g;
            float bv0 = bias[co0];
            float bv1 = bias[co0 + 8];
            float* o0 = out + (size_t)(b * COUT + co0) * (HH * WW) + y * WW;
            float* o1 = o0 + 8 * (HH * WW);
#pragma unroll
            for (int nt = 0; nt < 4; nt++) {
                int xc = (wn & 1) * 32 + nt * 8 + tig * 2;
                float2 nz = *(const float2*)(nzrow + xc);
                float nzx = nz.x * nw, nzy = nz.y * nw;
                float v0 = c[mt][nt][0] + nzx + bv0;
                float v1 = c[mt][nt][1] + nzy + bv0;
                float v2 = c[mt][nt][2] + nzx + bv1;
                float v3 = c[mt][nt][3] + nzy + bv1;
                v0 = (v0 > 0.f ? v0 : 0.2f * v0) * 1.41421356237309515f;
                v1 = (v1 > 0.f ? v1 : 0.2f * v1) * 1.41421356237309515f;
                v2 = (v2 > 0.f ? v2 : 0.2f * v2) * 1.41421356237309515f;
                v3 = (v3 > 0.f ? v3 : 0.2f * v3) * 1.41421356237309515f;
                *(float2*)(o0 + xc) = make_float2(v0, v1);
                *(float2*)(o1 + xc) = make_float2(v2, v3);
            }
        }
    }
}

// ---------------- launch ----------------
extern "C" void kernel_launch(void* const* d_in, const int* in_sizes, int n_in,
                              void* d_out, int out_size) {
    const float* x        = (const float*)d_in[0];
    const float* style    = (const float*)d_in[1];
    const float* noise    = (const float*)d_in[2];
    const float* weight   = (const float*)d_in[3];
    const float* style_w  = (const float*)d_in[4];
    const float* style_b  = (const float*)d_in[5];
    const float* bias     = (const float*)d_in[6];
    const float* nw       = (const float*)d_in[7];
    float* out = (float*)d_out;

    cudaFuncSetAttribute(conv_mma, cudaFuncAttributeMaxDynamicSharedMemorySize, SMEM_BYTES);

    fused1_kernel<<<272, 256>>>(style, style_w, style_b, weight);  // 1
    d_kernel<<<BATCH, 256>>>();                                    // 2
    wa_kernel<<<9216, 256>>>(weight);                              // 3
    conv_mma<<<dim3(32, 2, 16), 256, SMEM_BYTES>>>(x, noise, bias, nw, out);  // 4
}

// round 15
// speedup vs baseline: 2.5129x; 2.5129x over previous
#include <cuda_runtime.h>
#include <cuda_fp16.h>
#include <cstdint>

#define BATCH 16
#define CIN   256
#define COUT  256
#define HH    64
#define WW    64
#define LAT   512

// ---------------- scratch (device globals; no allocation) ----------------
__device__ __align__(16) float g_s[BATCH * CIN];
__device__ __align__(16) float g_d[BATCH * COUT];
__device__ __align__(16) float g_wss[CIN * COUT];
// fp16 A panels, fragment-major: [b][cot][c(24)][ks(6)][wm(2)][mt(4)][lane(32)] uint4
__device__ __align__(16) uint4 g_wA[(size_t)BATCH * 2 * 24 * 6 * 2 * 4 * 32];
// fp16 x, ci-pair packed: [b][ci2(128)][y(64)][x(64)] half2-as-uint
__device__ __align__(16) unsigned g_x16[(size_t)BATCH * 128 * HH * WW];

__device__ __forceinline__ unsigned h2u(__half2 h) {
    return *reinterpret_cast<unsigned*>(&h);
}

// ---------------- prep 1: style affine + wss + x->fp16 pack ----------------
__global__ void fused1_kernel(const float* __restrict__ style,
                              const float* __restrict__ style_w,
                              const float* __restrict__ style_b,
                              const float* __restrict__ weight,
                              const float* __restrict__ x) {
    if (blockIdx.x < 16) {
        __shared__ float st[LAT];
        int b = blockIdx.x, tid = threadIdx.x;
        st[tid]       = style[b * LAT + tid];
        st[tid + 256] = style[b * LAT + tid + 256];
        __syncthreads();
        float acc = style_b[tid];
#pragma unroll 8
        for (int l = 0; l < LAT; l++) acc += st[l] * style_w[l * CIN + tid];
        g_s[b * CIN + tid] = acc;
    } else if (blockIdx.x < 272) {
        int ci = blockIdx.x - 16, co = threadIdx.x;
        const float* wp = weight + co * (CIN * 9) + ci * 9;
        float s = 0.f;
#pragma unroll
        for (int t = 0; t < 9; t++) { float v = wp[t]; s += v * v; }
        g_wss[ci * COUT + co] = s;
    } else {
        int h = (blockIdx.x - 272) * 256 + threadIdx.x;   // 0 .. 16*128*4096-1
        int pix = h & 4095;
        int r   = h >> 12;            // b*128 + ci2
        int ci2 = r & 127;
        int b   = r >> 7;
        const float* p = x + (((size_t)(b * 256 + 2 * ci2)) << 12) + pix;
        g_x16[h] = h2u(__floats2half2_rn(p[0], p[4096]));
    }
}

__global__ void d_kernel() {
    __shared__ float s2[CIN];
    int b = blockIdx.x, co = threadIdx.x;
    float sv = g_s[b * CIN + co];
    s2[co] = sv * sv;
    __syncthreads();
    float acc = 1e-8f;
#pragma unroll 8
    for (int ci = 0; ci < CIN; ci++) acc += g_wss[ci * COUT + co] * s2[ci];
    g_d[b * COUT + co] = rsqrtf(acc);
}

// ---------------- prep 2: fp16 fragment-major modulated weights ----------------
// uint4 = {a0,a1,a2,a3} half2: a0=(m,k|k+1), a1=(m+8,..), a2=(m,k+8|k+9), a3=(m+8,..)
// chunk c covers taps (c%3)*3..+2 of ci-group c/3; ks: tap=(c%3)*3+(ks>>1), kwin=ks&1.
__global__ void wa_kernel(const float* __restrict__ weight) {
    int o = blockIdx.x * 256 + threadIdx.x;   // uint4 index, 1179648 -> 4608 blocks
    int lane = o & 31; int t = o >> 5;
    int mt = t & 3;  t >>= 2;
    int wm = t & 1;  t >>= 1;
    int ks = t % 6;  t /= 6;
    int c  = t % 24; t /= 24;
    int cot = t & 1; int b = t >> 1;
    int g = lane >> 2, tig = lane & 3;
    int cig = c / 3;
    int tap = (c % 3) * 3 + (ks >> 1);
    int ci  = cig * 32 + (ks & 1) * 16 + 2 * tig;
    int co  = cot * 128 + wm * 64 + mt * 16 + g;
    float d0 = g_d[b * COUT + co], d1 = g_d[b * COUT + co + 8];
    float s0 = g_s[b * CIN + ci],     s1 = g_s[b * CIN + ci + 1];
    float s8 = g_s[b * CIN + ci + 8], s9 = g_s[b * CIN + ci + 9];
    const float* wb = weight;
    float w00 = wb[(co * CIN + ci) * 9 + tap]       * s0 * d0;
    float w01 = wb[(co * CIN + ci + 1) * 9 + tap]   * s1 * d0;
    float w10 = wb[((co + 8) * CIN + ci) * 9 + tap]     * s0 * d1;
    float w11 = wb[((co + 8) * CIN + ci + 1) * 9 + tap] * s1 * d1;
    float w20 = wb[(co * CIN + ci + 8) * 9 + tap]   * s8 * d0;
    float w21 = wb[(co * CIN + ci + 9) * 9 + tap]   * s9 * d0;
    float w30 = wb[((co + 8) * CIN + ci + 8) * 9 + tap] * s8 * d1;
    float w31 = wb[((co + 8) * CIN + ci + 9) * 9 + tap] * s9 * d1;
    uint4 r;
    r.x = h2u(__floats2half2_rn(w00, w01));
    r.y = h2u(__floats2half2_rn(w10, w11));
    r.z = h2u(__floats2half2_rn(w20, w21));
    r.w = h2u(__floats2half2_rn(w30, w31));
    g_wA[o] = r;
}

// ---------------- main: fp16 m16n8k16, K=96 chunks, async pipeline ----------------
// CTA: M=128 co x N=128 px (2 rows). 8 warps (2x4), warp tile 64x32, 2 CTA/SM.
// 24 chunks of K=96 (3 taps x 2 k16-windows). A: 2-stage cp.async (24KB each).
// B: double-buffered fp16 ci-pair slab (18.5KB), prefetched in 4 pieces over
// the first 2 chunks of each cig. Barriers: 24 (one per chunk).
#define A_STAGE    24576               // 1536 uint4
#define SLAB_U     296                 // 4B units per ci2 (4*68 + pad); %32==8 -> conflict-free
#define SLAB_UNITS (16 * SLAB_U)       // 4736
#define SLAB_BYTES (SLAB_UNITS * 4)    // 18944
#define SMEM_BYTES (2 * A_STAGE + 2 * SLAB_BYTES)   // 87040 -> 2 CTAs/SM

#define CP16_CG(dst, src) \
    asm volatile("cp.async.cg.shared.global [%0], [%1], 16;" :: "r"(dst), "l"(src))
#define CP_COMMIT()   asm volatile("cp.async.commit_group;" ::: "memory")
#define CP_WAIT_ALL() asm volatile("cp.async.wait_group 0;" ::: "memory")

#define MMA_F16(c, a, b0, b1)                                                  \
    asm volatile("mma.sync.aligned.m16n8k16.row.col.f32.f16.f16.f32 "          \
        "{%0,%1,%2,%3}, {%4,%5,%6,%7}, {%8,%9}, {%0,%1,%2,%3};"                \
        : "+f"((c)[0]), "+f"((c)[1]), "+f"((c)[2]), "+f"((c)[3])               \
        : "r"((a).x), "r"((a).y), "r"((a).z), "r"((a).w), "r"(b0), "r"(b1))

__global__ void __launch_bounds__(256, 2)
conv_mma(const float* __restrict__ noise, const float* __restrict__ bias,
         const float* __restrict__ nwptr, float* __restrict__ out) {
    extern __shared__ __align__(16) char smem[];
    unsigned* slabu = (unsigned*)(smem + 2 * A_STAGE);
    const uint32_t sbase = (uint32_t)__cvta_generic_to_shared(smem);

    const int tid  = threadIdx.x;
    const int w    = tid >> 5;
    const int lane = tid & 31;
    const int g    = lane >> 2;
    const int tig  = lane & 3;
    const int wm   = w >> 2;
    const int wn   = w & 3;

    const int y0     = blockIdx.x * 2;
    const int coBase = blockIdx.y * 128;
    const int b      = blockIdx.z;

    const unsigned* x16b = g_x16 + (((size_t)b * 128) << 12);
    const uint4* wa4 = g_wA + ((size_t)(b * 2 + blockIdx.y)) * (24 * 1536);

    // zero both slabs once (pads + out-of-range rows stay zero forever)
    for (int i = tid; i < 2 * SLAB_UNITS / 4; i += 256)
        ((uint4*)slabu)[i] = make_uint4(0u, 0u, 0u, 0u);

    float c[4][4][4];
#pragma unroll
    for (int mt = 0; mt < 4; mt++)
#pragma unroll
        for (int nt = 0; nt < 4; nt++)
#pragma unroll
            for (int i = 0; i < 4; i++) c[mt][nt][i] = 0.f;

    auto load_A = [&](int ch, int buf) {
        const uint32_t abase = sbase + buf * A_STAGE;
        const uint4* src4 = wa4 + ch * 1536;
#pragma unroll
        for (int i = 0; i < 6; i++) {
            int idx = tid + 256 * i;
            CP16_CG(abase + idx * 16, src4 + idx);
        }
    };
    // one slab piece: 256 of the 1024 cp16 (rows (ci2,ry) 0..63 x 16 cp16)
    auto load_slab_piece = [&](int cig, int sb, int piece) {
        const uint32_t slbase = sbase + 2 * A_STAGE + sb * SLAB_BYTES;
        int o   = piece * 256 + tid;
        int row = o >> 4;              // (ci2,ry) pair 0..63
        int f   = o & 15;
        int ci2 = row >> 2;
        int ry  = row & 3;
        int y   = y0 - 1 + ry;
        if ((unsigned)y < HH) {
            const unsigned* src = x16b + (((size_t)(cig * 16 + ci2)) << 12) + y * WW + f * 4;
            CP16_CG(slbase + (ci2 * SLAB_U + ry * 68 + 4 + f * 4) * 4, src);
        }
    };

    __syncthreads();                   // zeroing visible before cp.async writes
    load_A(0, 0);
#pragma unroll
    for (int p = 0; p < 4; p++) load_slab_piece(0, 0, p);
    CP_COMMIT();
    CP_WAIT_ALL();
    __syncthreads();

    // B fragment base (4B/half2 units): ci2-part tig*SLAB_U, +3 halo offset
    const int bfrag0 = tig * SLAB_U + (wn >> 1) * 68 + (wn & 1) * 32 + g + 3;

    for (int ch = 0; ch < 24; ch++) {
        if (ch > 0) { CP_WAIT_ALL(); __syncthreads(); }

        const int cig = ch / 3;
        const int j   = ch - 3 * cig;          // 0..2
        if (ch + 1 < 24) load_A(ch + 1, (ch + 1) & 1);
        if (cig + 1 < 8) {
            if (j == 0)      { load_slab_piece(cig + 1, (cig + 1) & 1, 0);
                               load_slab_piece(cig + 1, (cig + 1) & 1, 1); }
            else if (j == 1) { load_slab_piece(cig + 1, (cig + 1) & 1, 2);
                               load_slab_piece(cig + 1, (cig + 1) & 1, 3); }
        }
        CP_COMMIT();

        const unsigned* sl = slabu + (cig & 1) * SLAB_UNITS;
        const uint4* Af = (const uint4*)(smem + (ch & 1) * A_STAGE);
        const int tapBase = j * 3;

#pragma unroll
        for (int ks = 0; ks < 6; ks++) {
            uint4 a[4];
#pragma unroll
            for (int mt = 0; mt < 4; mt++)
                a[mt] = Af[((ks * 2 + wm) * 4 + mt) * 32 + lane];
            const int tap = tapBase + (ks >> 1);
            const int ky = tap / 3;
            const int kx = tap - ky * 3;
            const unsigned* bk = sl + bfrag0 + ky * 68 + kx + (ks & 1) * (8 * SLAB_U);
            unsigned b0[4], b1[4];
#pragma unroll
            for (int nt = 0; nt < 4; nt++) {
                b0[nt] = bk[nt * 8];
                b1[nt] = bk[nt * 8 + 4 * SLAB_U];
            }
#pragma unroll
            for (int mt = 0; mt < 4; mt++)
#pragma unroll
                for (int nt = 0; nt < 4; nt++)
                    MMA_F16(c[mt][nt], a[mt], b0[nt], b1[nt]);
        }
    }

    // ---- epilogue: noise + bias + leaky_relu * sqrt(2) (same D layout as tf32)
    {
        const float nw = nwptr[0];
        const int y = y0 + (wn >> 1);
        const float* nzrow = noise + (size_t)b * (HH * WW) + y * WW;
#pragma unroll
        for (int mt = 0; mt < 4; mt++) {
            int co0 = coBase + wm * 64 + mt * 16 + g;
            float bv0 = bias[co0];
            float bv1 = bias[co0 + 8];
            float* o0 = out + (size_t)(b * COUT + co0) * (HH * WW) + y * WW;
            float* o1 = o0 + 8 * (HH * WW);
#pragma unroll
            for (int nt = 0; nt < 4; nt++) {
                int xc = (wn & 1) * 32 + nt * 8 + tig * 2;
                float2 nz = *(const float2*)(nzrow + xc);
                float nzx = nz.x * nw, nzy = nz.y * nw;
                float v0 = c[mt][nt][0] + nzx + bv0;
                float v1 = c[mt][nt][1] + nzy + bv0;
                float v2 = c[mt][nt][2] + nzx + bv1;
                float v3 = c[mt][nt][3] + nzy + bv1;
                v0 = (v0 > 0.f ? v0 : 0.2f * v0) * 1.41421356237309515f;
                v1 = (v1 > 0.f ? v1 : 0.2f * v1) * 1.41421356237309515f;
                v2 = (v2 > 0.f ? v2 : 0.2f * v2) * 1.41421356237309515f;
                v3 = (v3 > 0.f ? v3 : 0.2f * v3) * 1.41421356237309515f;
                *(float2*)(o0 + xc) = make_float2(v0, v1);
                *(float2*)(o1 + xc) = make_float2(v2, v3);
            }
        }
    }
}

// ---------------- launch ----------------
extern "C" void kernel_launch(void* const* d_in, const int* in_sizes, int n_in,
                              void* d_out, int out_size) {
    const float* x        = (const float*)d_in[0];
    const float* style    = (const float*)d_in[1];
    const float* noise    = (const float*)d_in[2];
    const float* weight   = (const float*)d_in[3];
    const float* style_w  = (const float*)d_in[4];
    const float* style_b  = (const float*)d_in[5];
    const float* bias     = (const float*)d_in[6];
    const float* nw       = (const float*)d_in[7];
    float* out = (float*)d_out;

    cudaFuncSetAttribute(conv_mma, cudaFuncAttributeMaxDynamicSharedMemorySize, SMEM_BYTES);

    fused1_kernel<<<272 + 32768, 256>>>(style, style_w, style_b, weight, x);  // 1
    d_kernel<<<BATCH, 256>>>();                                               // 2
    wa_kernel<<<4608, 256>>>(weight);                                         // 3
    conv_mma<<<dim3(32, 2, 16), 256, SMEM_BYTES>>>(noise, bias, nw, out);     // 4
}